// round 1
// baseline (speedup 1.0000x reference)
#include <cuda_runtime.h>
#include <cuda_bf16.h>
#include <math.h>

// ---------------------------------------------------------------------------
// Problem constants
// ---------------------------------------------------------------------------
#define BATCH   2048
#define T_SEQ   64
#define D_MODEL 384
#define NH      8
#define HS      48          // head size
#define D_FF    1536
#define M_TOK   (BATCH * T_SEQ)          // 131072 tokens
#define QKV_N   (3 * D_MODEL)            // 1152

// ---------------------------------------------------------------------------
// Scratch (static device globals -- no runtime allocation allowed)
// ---------------------------------------------------------------------------
__device__ float g_h1  [(size_t)M_TOK * D_MODEL];   // LN1(x)
__device__ float g_h2  [(size_t)M_TOK * D_MODEL];   // LN2(res)
__device__ float g_attn[(size_t)M_TOK * D_MODEL];   // attention output (pre-proj)
__device__ float g_res [(size_t)M_TOK * D_MODEL];   // h1 + proj(attn)
__device__ float g_big [(size_t)M_TOK * D_FF];      // qkv (first M*1152) then ff-mid
__device__ float g_Wqkv[(size_t)D_MODEL * QKV_N];   // packed [384 x 1152]
__device__ float g_bqkv[QKV_N];

// ---------------------------------------------------------------------------
// Pack per-head QKV weights (h,d,e) -> standard [K=384, N=1152] row-major
// col = which*384 + h*48 + e
// ---------------------------------------------------------------------------
__global__ void pack_qkv_kernel(const float* __restrict__ wq, const float* __restrict__ wk,
                                const float* __restrict__ wv, const float* __restrict__ bq,
                                const float* __restrict__ bk, const float* __restrict__ bv) {
    int i = blockIdx.x * blockDim.x + threadIdx.x;
    const int total = D_MODEL * QKV_N;
    if (i < total) {
        int d    = i / QKV_N;
        int col  = i % QKV_N;
        int which = col / D_MODEL;
        int hc    = col % D_MODEL;
        int h = hc / HS, e = hc % HS;
        const float* w = (which == 0) ? wq : (which == 1) ? wk : wv;
        g_Wqkv[i] = w[(size_t)h * D_MODEL * HS + (size_t)d * HS + e];
    }
    if (i < QKV_N) {
        int which = i / D_MODEL;
        int hc    = i % D_MODEL;
        int h = hc / HS, e = hc % HS;
        const float* bsrc = (which == 0) ? bq : (which == 1) ? bk : bv;
        g_bqkv[i] = bsrc[h * HS + e];
    }
}

// ---------------------------------------------------------------------------
// LayerNorm: one warp per token row (D=384 = 32 lanes * 3 float4)
// ---------------------------------------------------------------------------
__global__ void ln_kernel(const float* __restrict__ in, const float* __restrict__ gain,
                          const float* __restrict__ bias, float* __restrict__ out) {
    int warp = (blockIdx.x * blockDim.x + threadIdx.x) >> 5;
    int lane = threadIdx.x & 31;
    if (warp >= M_TOK) return;
    const float4* row = (const float4*)(in + (size_t)warp * D_MODEL);
    float4 v[3];
    float s = 0.f, s2 = 0.f;
#pragma unroll
    for (int j = 0; j < 3; j++) {
        v[j] = row[lane + 32 * j];
        s  += v[j].x + v[j].y + v[j].z + v[j].w;
        s2 += v[j].x * v[j].x + v[j].y * v[j].y + v[j].z * v[j].z + v[j].w * v[j].w;
    }
#pragma unroll
    for (int o = 16; o; o >>= 1) {
        s  += __shfl_xor_sync(0xffffffffu, s,  o);
        s2 += __shfl_xor_sync(0xffffffffu, s2, o);
    }
    float mean = s * (1.0f / D_MODEL);
    float var  = s2 * (1.0f / D_MODEL) - mean * mean;
    float inv  = rsqrtf(var + 1e-5f);
    float4* orow = (float4*)(out + (size_t)warp * D_MODEL);
#pragma unroll
    for (int j = 0; j < 3; j++) {
        int idx = lane + 32 * j;
        float4 g4 = ((const float4*)gain)[idx];
        float4 b4 = ((const float4*)bias)[idx];
        float4 o;
        o.x = (v[j].x - mean) * inv * g4.x + b4.x;
        o.y = (v[j].y - mean) * inv * g4.y + b4.y;
        o.z = (v[j].z - mean) * inv * g4.z + b4.z;
        o.w = (v[j].w - mean) * inv * g4.w + b4.w;
        orow[idx] = o;
    }
}

// ---------------------------------------------------------------------------
// SGEMM: C[M,N] = A[M,K] @ W[K,N] (+bias[N]) (relu) (+Res[M,N])
// 128x128 tile, BK=8, 256 threads, 8x8 per thread. All dims divide exactly.
// grid = (N/128, M/128)
// ---------------------------------------------------------------------------
template <bool BIAS, bool RES, bool RELU>
__global__ __launch_bounds__(256, 2)
void sgemm_kernel(const float* __restrict__ A, const float* __restrict__ W,
                  const float* __restrict__ bias, const float* __restrict__ Rsd,
                  float* __restrict__ C, int N, int K) {
    __shared__ float As[8][128];
    __shared__ float Bs[8][128];

    const int tid = threadIdx.x;
    const int bn = blockIdx.x * 128;
    const int bm = blockIdx.y * 128;

    // global load indices
    const int ar = tid >> 1;          // 0..127 (A row within tile)
    const int ac = (tid & 1) * 4;     // 0 or 4 (A col within BK)
    const int br = tid >> 5;          // 0..7   (W row within BK)
    const int bc = (tid & 31) * 4;    // 0..124 (W col within tile)

    const float* Aptr = A + (size_t)(bm + ar) * K + ac;
    const float* Wptr = W + (size_t)br * N + bn + bc;

    const int tx = tid & 15;          // col group
    const int ty = tid >> 4;          // row group

    float acc[8][8];
#pragma unroll
    for (int i = 0; i < 8; i++)
#pragma unroll
        for (int j = 0; j < 8; j++) acc[i][j] = 0.f;

    for (int k0 = 0; k0 < K; k0 += 8) {
        float4 a4 = *(const float4*)Aptr;  Aptr += 8;
        float4 b4 = *(const float4*)Wptr;  Wptr += (size_t)8 * N;
        __syncthreads();
        As[ac + 0][ar] = a4.x;
        As[ac + 1][ar] = a4.y;
        As[ac + 2][ar] = a4.z;
        As[ac + 3][ar] = a4.w;
        *(float4*)&Bs[br][bc] = b4;
        __syncthreads();
#pragma unroll
        for (int k = 0; k < 8; k++) {
            float a[8], b[8];
            *(float4*)(a)     = *(float4*)&As[k][ty * 8];
            *(float4*)(a + 4) = *(float4*)&As[k][ty * 8 + 4];
            *(float4*)(b)     = *(float4*)&Bs[k][tx * 8];
            *(float4*)(b + 4) = *(float4*)&Bs[k][tx * 8 + 4];
#pragma unroll
            for (int i = 0; i < 8; i++)
#pragma unroll
                for (int j = 0; j < 8; j++) acc[i][j] += a[i] * b[j];
        }
    }

    // epilogue
#pragma unroll
    for (int i = 0; i < 8; i++) {
        int row = bm + ty * 8 + i;
        float* crow = C + (size_t)row * N;
        const float* rrow = RES ? (Rsd + (size_t)row * N) : nullptr;
#pragma unroll
        for (int jj = 0; jj < 8; jj += 4) {
            int col = bn + tx * 8 + jj;
            float4 v = make_float4(acc[i][jj], acc[i][jj + 1], acc[i][jj + 2], acc[i][jj + 3]);
            if (BIAS) {
                float4 b4 = *(const float4*)&bias[col];
                v.x += b4.x; v.y += b4.y; v.z += b4.z; v.w += b4.w;
            }
            if (RELU) {
                v.x = fmaxf(v.x, 0.f); v.y = fmaxf(v.y, 0.f);
                v.z = fmaxf(v.z, 0.f); v.w = fmaxf(v.w, 0.f);
            }
            if (RES) {
                float4 r4 = *(const float4*)&rrow[col];
                v.x += r4.x; v.y += r4.y; v.z += r4.z; v.w += r4.w;
            }
            *(float4*)&crow[col] = v;
        }
    }
}

// ---------------------------------------------------------------------------
// Causal attention: one CTA (64 threads) per (batch, head).
// q in registers, k/v/exp-scores in smem (padded, conflict-free).
// ---------------------------------------------------------------------------
__global__ __launch_bounds__(64) void attn_kernel(float* __restrict__ out) {
    const int bh = blockIdx.x;
    const int b = bh >> 3;
    const int h = bh & 7;
    const float* qkv = g_big;

    __shared__ float ks[T_SEQ][HS + 1];
    __shared__ float vs[T_SEQ][HS + 1];
    __shared__ float es[T_SEQ][T_SEQ + 1];

    const int tid = threadIdx.x;

    // cooperative load of K, V tiles
    for (int i = tid; i < T_SEQ * HS; i += 64) {
        int r = i / HS, e = i % HS;
        size_t base = (size_t)(b * T_SEQ + r) * QKV_N + h * HS + e;
        ks[r][e] = qkv[base + D_MODEL];
        vs[r][e] = qkv[base + 2 * D_MODEL];
    }
    __syncthreads();

    const int t = tid;
    const size_t qbase = (size_t)(b * T_SEQ + t) * QKV_N + h * HS;
    float q[HS];
#pragma unroll
    for (int e4 = 0; e4 < HS; e4 += 4) {
        float4 q4 = *(const float4*)&qkv[qbase + e4];
        q[e4] = q4.x; q[e4 + 1] = q4.y; q[e4 + 2] = q4.z; q[e4 + 3] = q4.w;
    }

    const float scale = 0.14433756729740643f;  // 1/sqrt(48)
    float mx = -1e30f;
    for (int s = 0; s <= t; s++) {
        float d = 0.f;
#pragma unroll
        for (int e = 0; e < HS; e++) d += q[e] * ks[s][e];
        d *= scale;
        es[t][s] = d;
        mx = fmaxf(mx, d);
    }
    float sum = 0.f;
    for (int s = 0; s <= t; s++) {
        float p = __expf(es[t][s] - mx);
        es[t][s] = p;
        sum += p;
    }
    const float inv = 1.0f / sum;

    float acc[HS];
#pragma unroll
    for (int e = 0; e < HS; e++) acc[e] = 0.f;
    for (int s = 0; s <= t; s++) {
        float p = es[t][s];
#pragma unroll
        for (int e = 0; e < HS; e++) acc[e] += p * vs[s][e];
    }

    const size_t ob = (size_t)(b * T_SEQ + t) * D_MODEL + h * HS;
#pragma unroll
    for (int e4 = 0; e4 < HS; e4 += 4) {
        float4 o = make_float4(acc[e4] * inv, acc[e4 + 1] * inv,
                               acc[e4 + 2] * inv, acc[e4 + 3] * inv);
        *(float4*)&out[ob + e4] = o;
    }
}

// ---------------------------------------------------------------------------
// Launcher
// ---------------------------------------------------------------------------
extern "C" void kernel_launch(void* const* d_in, const int* in_sizes, int n_in,
                              void* d_out, int out_size) {
    (void)in_sizes; (void)n_in; (void)out_size;
    const float* x  = (const float*)d_in[0];
    const float* wq = (const float*)d_in[1];
    const float* bq = (const float*)d_in[2];
    const float* wk = (const float*)d_in[3];
    const float* bk = (const float*)d_in[4];
    const float* wv = (const float*)d_in[5];
    const float* bv = (const float*)d_in[6];
    const float* wo = (const float*)d_in[7];
    const float* bo = (const float*)d_in[8];
    const float* w1 = (const float*)d_in[9];
    const float* b1 = (const float*)d_in[10];
    const float* w2 = (const float*)d_in[11];
    const float* b2 = (const float*)d_in[12];
    const float* g1 = (const float*)d_in[13];
    const float* be1 = (const float*)d_in[14];
    const float* g2 = (const float*)d_in[15];
    const float* be2 = (const float*)d_in[16];
    float* out = (float*)d_out;

    float *p_h1, *p_h2, *p_attn, *p_res, *p_big, *p_Wqkv, *p_bqkv;
    cudaGetSymbolAddress((void**)&p_h1, g_h1);
    cudaGetSymbolAddress((void**)&p_h2, g_h2);
    cudaGetSymbolAddress((void**)&p_attn, g_attn);
    cudaGetSymbolAddress((void**)&p_res, g_res);
    cudaGetSymbolAddress((void**)&p_big, g_big);
    cudaGetSymbolAddress((void**)&p_Wqkv, g_Wqkv);
    cudaGetSymbolAddress((void**)&p_bqkv, g_bqkv);

    // 1. pack QKV weights
    pack_qkv_kernel<<<(D_MODEL * QKV_N + 255) / 256, 256>>>(wq, wk, wv, bq, bk, bv);

    // 2. LN1: x -> h1
    ln_kernel<<<(M_TOK * 32) / 256, 256>>>(x, g1, be1, p_h1);

    // 3. QKV GEMM: h1[131072,384] @ Wqkv[384,1152] + b -> g_big
    sgemm_kernel<true, false, false><<<dim3(QKV_N / 128, M_TOK / 128), 256>>>(
        p_h1, p_Wqkv, p_bqkv, nullptr, p_big, QKV_N, D_MODEL);

    // 4. causal attention per (batch, head) -> g_attn
    attn_kernel<<<BATCH * NH, 64>>>(p_attn);

    // 5. output projection + residual: attn @ wo + bo + h1 -> g_res
    sgemm_kernel<true, true, false><<<dim3(D_MODEL / 128, M_TOK / 128), 256>>>(
        p_attn, wo, bo, p_h1, p_res, D_MODEL, D_MODEL);

    // 6. LN2: res -> h2
    ln_kernel<<<(M_TOK * 32) / 256, 256>>>(p_res, g2, be2, p_h2);

    // 7. FF1 + ReLU: h2 @ w1 + b1 -> g_big (ff mid)
    sgemm_kernel<true, false, true><<<dim3(D_FF / 128, M_TOK / 128), 256>>>(
        p_h2, w1, b1, nullptr, p_big, D_FF, D_MODEL);

    // 8. FF2 + bias + residual: big @ w2 + b2 + h2 -> out
    sgemm_kernel<true, true, false><<<dim3(D_MODEL / 128, M_TOK / 128), 256>>>(
        p_big, w2, b2, p_h2, out, D_MODEL, D_FF);
}

// round 2
// speedup vs baseline: 2.3712x; 2.3712x over previous
#include <cuda_runtime.h>
#include <cuda_bf16.h>
#include <math.h>
#include <stdint.h>

// ---------------------------------------------------------------------------
// Problem constants
// ---------------------------------------------------------------------------
#define BATCH   2048
#define T_SEQ   64
#define D_MODEL 384
#define NH      8
#define HS      48
#define D_FF    1536
#define M_TOK   (BATCH * T_SEQ)          // 131072
#define QKV_N   (3 * D_MODEL)            // 1152

// ---------------------------------------------------------------------------
// Scratch
// ---------------------------------------------------------------------------
__device__ float g_h1  [(size_t)M_TOK * D_MODEL];
__device__ float g_h2  [(size_t)M_TOK * D_MODEL];
__device__ float g_attn[(size_t)M_TOK * D_MODEL];
__device__ float g_res [(size_t)M_TOK * D_MODEL];
__device__ float g_big [(size_t)M_TOK * D_FF];
__device__ float g_Wqkv[(size_t)D_MODEL * QKV_N];
__device__ float g_bqkv[QKV_N];

// ---------------------------------------------------------------------------
// Pack per-head QKV weights -> [K=384, N=1152] row-major
// ---------------------------------------------------------------------------
__global__ void pack_qkv_kernel(const float* __restrict__ wq, const float* __restrict__ wk,
                                const float* __restrict__ wv, const float* __restrict__ bq,
                                const float* __restrict__ bk, const float* __restrict__ bv) {
    int i = blockIdx.x * blockDim.x + threadIdx.x;
    const int total = D_MODEL * QKV_N;
    if (i < total) {
        int d    = i / QKV_N;
        int col  = i % QKV_N;
        int which = col / D_MODEL;
        int hc    = col % D_MODEL;
        int h = hc / HS, e = hc % HS;
        const float* w = (which == 0) ? wq : (which == 1) ? wk : wv;
        g_Wqkv[i] = w[(size_t)h * D_MODEL * HS + (size_t)d * HS + e];
    }
    if (i < QKV_N) {
        int which = i / D_MODEL;
        int hc    = i % D_MODEL;
        int h = hc / HS, e = hc % HS;
        const float* bsrc = (which == 0) ? bq : (which == 1) ? bk : bv;
        g_bqkv[i] = bsrc[h * HS + e];
    }
}

// ---------------------------------------------------------------------------
// LayerNorm: one warp per token row
// ---------------------------------------------------------------------------
__global__ void ln_kernel(const float* __restrict__ in, const float* __restrict__ gain,
                          const float* __restrict__ bias, float* __restrict__ out) {
    int warp = (blockIdx.x * blockDim.x + threadIdx.x) >> 5;
    int lane = threadIdx.x & 31;
    if (warp >= M_TOK) return;
    const float4* row = (const float4*)(in + (size_t)warp * D_MODEL);
    float4 v[3];
    float s = 0.f, s2 = 0.f;
#pragma unroll
    for (int j = 0; j < 3; j++) {
        v[j] = row[lane + 32 * j];
        s  += v[j].x + v[j].y + v[j].z + v[j].w;
        s2 += v[j].x * v[j].x + v[j].y * v[j].y + v[j].z * v[j].z + v[j].w * v[j].w;
    }
#pragma unroll
    for (int o = 16; o; o >>= 1) {
        s  += __shfl_xor_sync(0xffffffffu, s,  o);
        s2 += __shfl_xor_sync(0xffffffffu, s2, o);
    }
    float mean = s * (1.0f / D_MODEL);
    float var  = s2 * (1.0f / D_MODEL) - mean * mean;
    float inv  = rsqrtf(var + 1e-5f);
    float4* orow = (float4*)(out + (size_t)warp * D_MODEL);
#pragma unroll
    for (int j = 0; j < 3; j++) {
        int idx = lane + 32 * j;
        float4 g4 = ((const float4*)gain)[idx];
        float4 b4 = ((const float4*)bias)[idx];
        float4 o;
        o.x = (v[j].x - mean) * inv * g4.x + b4.x;
        o.y = (v[j].y - mean) * inv * g4.y + b4.y;
        o.z = (v[j].z - mean) * inv * g4.z + b4.z;
        o.w = (v[j].w - mean) * inv * g4.w + b4.w;
        orow[idx] = o;
    }
}

// ---------------------------------------------------------------------------
// TF32 tensor-core GEMM: C[M,N] = A[M,K]@W[K,N] (+bias)(relu)(+res)
// 128x128 tile, BK=16, 256 threads (8 warps, 2x4), warp tile 64x32.
// mma.sync.aligned.m16n8k8.row.col.f32.tf32.tf32.f32
// ---------------------------------------------------------------------------
#define AS_STRIDE 20    // [m][k] padded: conflict-free fragment loads
#define BS_STRIDE 136   // [k][n] padded: conflict-free fragment loads

__device__ __forceinline__ uint32_t f2tf32(float f) {
    uint32_t u;
    asm("cvt.rna.tf32.f32 %0, %1;" : "=r"(u) : "f"(f));
    return u;
}

__device__ __forceinline__ void mma_tf32(float c[4], const uint32_t a[4], const uint32_t b[2]) {
    asm volatile(
        "mma.sync.aligned.m16n8k8.row.col.f32.tf32.tf32.f32 "
        "{%0,%1,%2,%3}, {%4,%5,%6,%7}, {%8,%9}, {%0,%1,%2,%3};"
        : "+f"(c[0]), "+f"(c[1]), "+f"(c[2]), "+f"(c[3])
        : "r"(a[0]), "r"(a[1]), "r"(a[2]), "r"(a[3]), "r"(b[0]), "r"(b[1]));
}

template <bool BIAS, bool RES, bool RELU>
__global__ __launch_bounds__(256)
void tgemm_kernel(const float* __restrict__ A, const float* __restrict__ W,
                  const float* __restrict__ bias, const float* __restrict__ Rsd,
                  float* __restrict__ C, int N, int K) {
    __shared__ uint32_t As[2][128 * AS_STRIDE];
    __shared__ uint32_t Bs[2][16 * BS_STRIDE];

    const int tid  = threadIdx.x;
    const int lane = tid & 31;
    const int warp = tid >> 5;
    const int warp_m = warp & 1;    // 2 warps along M (64 each)
    const int warp_n = warp >> 1;   // 4 warps along N (32 each)

    const int bm = blockIdx.y * 128;
    const int bn = blockIdx.x * 128;

    // --- global load mapping ---
    const int a_row = tid >> 1;            // 0..127
    const int a_col = (tid & 1) * 8;       // 0 or 8
    const int b_row = tid >> 4;            // 0..15 (k)
    const int b_col = (tid & 15) * 8;      // 0..120

    const float* Ag = A + (size_t)(bm + a_row) * K + a_col;
    const float* Bg = W + (size_t)b_row * N + bn + b_col;

    float4 pa0, pa1, pb0, pb1;

    // preload tile 0
    pa0 = *(const float4*)Ag;       pa1 = *(const float4*)(Ag + 4);
    pb0 = *(const float4*)Bg;       pb1 = *(const float4*)(Bg + 4);
    {
        uint32_t* as = &As[0][a_row * AS_STRIDE + a_col];
        as[0] = f2tf32(pa0.x); as[1] = f2tf32(pa0.y); as[2] = f2tf32(pa0.z); as[3] = f2tf32(pa0.w);
        as[4] = f2tf32(pa1.x); as[5] = f2tf32(pa1.y); as[6] = f2tf32(pa1.z); as[7] = f2tf32(pa1.w);
        uint32_t* bs = &Bs[0][b_row * BS_STRIDE + b_col];
        bs[0] = f2tf32(pb0.x); bs[1] = f2tf32(pb0.y); bs[2] = f2tf32(pb0.z); bs[3] = f2tf32(pb0.w);
        bs[4] = f2tf32(pb1.x); bs[5] = f2tf32(pb1.y); bs[6] = f2tf32(pb1.z); bs[7] = f2tf32(pb1.w);
    }
    __syncthreads();

    float acc[4][4][4];
#pragma unroll
    for (int i = 0; i < 4; i++)
#pragma unroll
        for (int j = 0; j < 4; j++)
#pragma unroll
            for (int r = 0; r < 4; r++) acc[i][j][r] = 0.f;

    int buf = 0;
    for (int k0 = 0; k0 < K; k0 += 16) {
        const bool last = (k0 + 16 >= K);
        if (!last) {
            const float* Agn = Ag + (k0 + 16);
            const float* Bgn = Bg + (size_t)(k0 + 16) * N;
            pa0 = *(const float4*)Agn;      pa1 = *(const float4*)(Agn + 4);
            pb0 = *(const float4*)Bgn;      pb1 = *(const float4*)(Bgn + 4);
        }

        // compute current buffer
        const uint32_t* as = As[buf];
        const uint32_t* bs = Bs[buf];
#pragma unroll
        for (int ks = 0; ks < 16; ks += 8) {
            uint32_t afr[4][4];
            uint32_t bfr[4][2];
#pragma unroll
            for (int mt = 0; mt < 4; mt++) {
                int m = warp_m * 64 + mt * 16 + (lane >> 2);
                int k = ks + (lane & 3);
                afr[mt][0] = as[m * AS_STRIDE + k];
                afr[mt][1] = as[(m + 8) * AS_STRIDE + k];
                afr[mt][2] = as[m * AS_STRIDE + k + 4];
                afr[mt][3] = as[(m + 8) * AS_STRIDE + k + 4];
            }
#pragma unroll
            for (int nt = 0; nt < 4; nt++) {
                int n = warp_n * 32 + nt * 8 + (lane >> 2);
                int k = ks + (lane & 3);
                bfr[nt][0] = bs[k * BS_STRIDE + n];
                bfr[nt][1] = bs[(k + 4) * BS_STRIDE + n];
            }
#pragma unroll
            for (int mt = 0; mt < 4; mt++)
#pragma unroll
                for (int nt = 0; nt < 4; nt++)
                    mma_tf32(acc[mt][nt], afr[mt], bfr[nt]);
        }

        if (!last) {
            uint32_t* asw = &As[buf ^ 1][a_row * AS_STRIDE + a_col];
            asw[0] = f2tf32(pa0.x); asw[1] = f2tf32(pa0.y); asw[2] = f2tf32(pa0.z); asw[3] = f2tf32(pa0.w);
            asw[4] = f2tf32(pa1.x); asw[5] = f2tf32(pa1.y); asw[6] = f2tf32(pa1.z); asw[7] = f2tf32(pa1.w);
            uint32_t* bsw = &Bs[buf ^ 1][b_row * BS_STRIDE + b_col];
            bsw[0] = f2tf32(pb0.x); bsw[1] = f2tf32(pb0.y); bsw[2] = f2tf32(pb0.z); bsw[3] = f2tf32(pb0.w);
            bsw[4] = f2tf32(pb1.x); bsw[5] = f2tf32(pb1.y); bsw[6] = f2tf32(pb1.z); bsw[7] = f2tf32(pb1.w);
            __syncthreads();
            buf ^= 1;
        }
    }

    // epilogue
#pragma unroll
    for (int mt = 0; mt < 4; mt++) {
#pragma unroll
        for (int nt = 0; nt < 4; nt++) {
            int r0 = bm + warp_m * 64 + mt * 16 + (lane >> 2);
            int col = bn + warp_n * 32 + nt * 8 + (lane & 3) * 2;
#pragma unroll
            for (int half = 0; half < 2; half++) {
                int row = r0 + half * 8;
                float vx = acc[mt][nt][half * 2 + 0];
                float vy = acc[mt][nt][half * 2 + 1];
                if (BIAS) {
                    float2 b2 = *(const float2*)&bias[col];
                    vx += b2.x; vy += b2.y;
                }
                if (RELU) { vx = fmaxf(vx, 0.f); vy = fmaxf(vy, 0.f); }
                if (RES) {
                    float2 r2 = *(const float2*)&Rsd[(size_t)row * N + col];
                    vx += r2.x; vy += r2.y;
                }
                *(float2*)&C[(size_t)row * N + col] = make_float2(vx, vy);
            }
        }
    }
}

// ---------------------------------------------------------------------------
// Causal attention: one CTA (128 threads) per (batch, head).
// Two lanes per query row t (each owns 24 of 48 e-dims).
// ---------------------------------------------------------------------------
__global__ __launch_bounds__(128) void attn_kernel(float* __restrict__ out) {
    const int bh = blockIdx.x;
    const int b = bh >> 3;
    const int h = bh & 7;
    const float* qkv = g_big;

    __shared__ float ks[T_SEQ][HS + 1];
    __shared__ float vs[T_SEQ][HS + 1];
    __shared__ float es[T_SEQ][T_SEQ + 1];

    const int tid = threadIdx.x;

    for (int i = tid; i < T_SEQ * HS; i += 128) {
        int r = i / HS, e = i % HS;
        size_t base = (size_t)(b * T_SEQ + r) * QKV_N + h * HS + e;
        ks[r][e] = qkv[base + D_MODEL];
        vs[r][e] = qkv[base + 2 * D_MODEL];
    }
    __syncthreads();

    const int t    = tid >> 1;
    const int half = tid & 1;
    const int eoff = half * 24;
    const unsigned pairmask = 0x3u << (tid & 30 & 31);  // the two lanes of this pair

    const size_t qbase = (size_t)(b * T_SEQ + t) * QKV_N + h * HS + eoff;
    float q[24];
#pragma unroll
    for (int e4 = 0; e4 < 24; e4 += 4) {
        float4 q4 = *(const float4*)&qkv[qbase + e4];
        q[e4] = q4.x; q[e4 + 1] = q4.y; q[e4 + 2] = q4.z; q[e4 + 3] = q4.w;
    }

    const float scale = 0.14433756729740643f;  // 1/sqrt(48)
    float mx = -1e30f;
    for (int s = 0; s <= t; s++) {
        float part = 0.f;
#pragma unroll
        for (int e = 0; e < 24; e++) part += q[e] * ks[s][eoff + e];
        float d = (part + __shfl_xor_sync(pairmask, part, 1)) * scale;
        if (!half) es[t][s] = d;
        mx = fmaxf(mx, d);
    }
    __syncwarp();

    float sum = 0.f;
    float acc[24];
#pragma unroll
    for (int e = 0; e < 24; e++) acc[e] = 0.f;
    for (int s = 0; s <= t; s++) {
        float p = __expf(es[t][s] - mx);
        sum += p;
#pragma unroll
        for (int e = 0; e < 24; e++) acc[e] += p * vs[s][eoff + e];
    }
    const float inv = 1.0f / sum;

    const size_t ob = (size_t)(b * T_SEQ + t) * D_MODEL + h * HS + eoff;
#pragma unroll
    for (int e4 = 0; e4 < 24; e4 += 4) {
        float4 o = make_float4(acc[e4] * inv, acc[e4 + 1] * inv,
                               acc[e4 + 2] * inv, acc[e4 + 3] * inv);
        *(float4*)&out[ob + e4] = o;
    }
}

// ---------------------------------------------------------------------------
// Launcher
// ---------------------------------------------------------------------------
extern "C" void kernel_launch(void* const* d_in, const int* in_sizes, int n_in,
                              void* d_out, int out_size) {
    (void)in_sizes; (void)n_in; (void)out_size;
    const float* x  = (const float*)d_in[0];
    const float* wq = (const float*)d_in[1];
    const float* bq = (const float*)d_in[2];
    const float* wk = (const float*)d_in[3];
    const float* bk = (const float*)d_in[4];
    const float* wv = (const float*)d_in[5];
    const float* bv = (const float*)d_in[6];
    const float* wo = (const float*)d_in[7];
    const float* bo = (const float*)d_in[8];
    const float* w1 = (const float*)d_in[9];
    const float* b1 = (const float*)d_in[10];
    const float* w2 = (const float*)d_in[11];
    const float* b2 = (const float*)d_in[12];
    const float* g1 = (const float*)d_in[13];
    const float* be1 = (const float*)d_in[14];
    const float* g2 = (const float*)d_in[15];
    const float* be2 = (const float*)d_in[16];
    float* out = (float*)d_out;

    float *p_h1, *p_h2, *p_attn, *p_res, *p_big, *p_Wqkv, *p_bqkv;
    cudaGetSymbolAddress((void**)&p_h1, g_h1);
    cudaGetSymbolAddress((void**)&p_h2, g_h2);
    cudaGetSymbolAddress((void**)&p_attn, g_attn);
    cudaGetSymbolAddress((void**)&p_res, g_res);
    cudaGetSymbolAddress((void**)&p_big, g_big);
    cudaGetSymbolAddress((void**)&p_Wqkv, g_Wqkv);
    cudaGetSymbolAddress((void**)&p_bqkv, g_bqkv);

    // 1. pack QKV weights
    pack_qkv_kernel<<<(D_MODEL * QKV_N + 255) / 256, 256>>>(wq, wk, wv, bq, bk, bv);

    // 2. LN1
    ln_kernel<<<(M_TOK * 32) / 256, 256>>>(x, g1, be1, p_h1);

    // 3. QKV GEMM (tf32 MMA)
    tgemm_kernel<true, false, false><<<dim3(QKV_N / 128, M_TOK / 128), 256>>>(
        p_h1, p_Wqkv, p_bqkv, nullptr, p_big, QKV_N, D_MODEL);

    // 4. attention
    attn_kernel<<<BATCH * NH, 128>>>(p_attn);

    // 5. output projection + residual
    tgemm_kernel<true, true, false><<<dim3(D_MODEL / 128, M_TOK / 128), 256>>>(
        p_attn, wo, bo, p_h1, p_res, D_MODEL, D_MODEL);

    // 6. LN2
    ln_kernel<<<(M_TOK * 32) / 256, 256>>>(p_res, g2, be2, p_h2);

    // 7. FF1 + ReLU
    tgemm_kernel<true, false, true><<<dim3(D_FF / 128, M_TOK / 128), 256>>>(
        p_h2, w1, b1, nullptr, p_big, D_FF, D_MODEL);

    // 8. FF2 + bias + residual
    tgemm_kernel<true, true, false><<<dim3(D_MODEL / 128, M_TOK / 128), 256>>>(
        p_big, w2, b2, p_h2, out, D_MODEL, D_FF);
}

// round 5
// speedup vs baseline: 4.5132x; 1.9033x over previous
#include <cuda_runtime.h>
#include <cuda_bf16.h>
#include <math.h>
#include <stdint.h>

// ---------------------------------------------------------------------------
// Problem constants
// ---------------------------------------------------------------------------
#define BATCH   2048
#define T_SEQ   64
#define D_MODEL 384
#define NH      8
#define HS      48
#define D_FF    1536
#define M_TOK   (BATCH * T_SEQ)          // 131072
#define QKV_N   (3 * D_MODEL)            // 1152

// ---------------------------------------------------------------------------
// Scratch (static device globals)
// ---------------------------------------------------------------------------
__device__ float          g_h1  [(size_t)M_TOK * D_MODEL];
__device__ __nv_bfloat16  g_h1b [(size_t)M_TOK * D_MODEL];
__device__ float          g_h2  [(size_t)M_TOK * D_MODEL];
__device__ __nv_bfloat16  g_h2b [(size_t)M_TOK * D_MODEL];
__device__ float          g_res [(size_t)M_TOK * D_MODEL];
__device__ float          g_big [(size_t)M_TOK * QKV_N];    // QKV fp32
__device__ __nv_bfloat16  g_attnb[(size_t)M_TOK * D_MODEL]; // attn out bf16
__device__ __nv_bfloat16  g_midb[(size_t)M_TOK * D_FF];     // FF mid bf16
__device__ __nv_bfloat16  g_WqkvT[(size_t)QKV_N * D_MODEL]; // [1152][384] bf16
__device__ float          g_bqkv [QKV_N];
__device__ __nv_bfloat16  g_WoT  [(size_t)D_MODEL * D_MODEL];
__device__ __nv_bfloat16  g_W1T  [(size_t)D_FF * D_MODEL];
__device__ __nv_bfloat16  g_W2T  [(size_t)D_MODEL * D_FF];

// ---------------------------------------------------------------------------
// Helpers
// ---------------------------------------------------------------------------
__device__ __forceinline__ uint32_t smem_u32(const void* p) {
    uint32_t a;
    asm("{ .reg .u64 t; cvta.to.shared.u64 t, %1; cvt.u32.u64 %0, t; }" : "=r"(a) : "l"(p));
    return a;
}
__device__ __forceinline__ void cp16(uint32_t dst, const void* src) {
    asm volatile("cp.async.cg.shared.global [%0], [%1], 16;" :: "r"(dst), "l"(src));
}
__device__ __forceinline__ void mma_bf16(float* c, const uint32_t* a, const uint32_t* b) {
    asm volatile(
        "mma.sync.aligned.m16n8k16.row.col.f32.bf16.bf16.f32 "
        "{%0,%1,%2,%3}, {%4,%5,%6,%7}, {%8,%9}, {%0,%1,%2,%3};"
        : "+f"(c[0]), "+f"(c[1]), "+f"(c[2]), "+f"(c[3])
        : "r"(a[0]), "r"(a[1]), "r"(a[2]), "r"(a[3]), "r"(b[0]), "r"(b[1]));
}

// ---------------------------------------------------------------------------
// Weight repack kernels (fp32 -> bf16, transposed to [N][K] K-major)
// ---------------------------------------------------------------------------
__global__ void pack_qkvT_kernel(const float* __restrict__ wq, const float* __restrict__ wk,
                                 const float* __restrict__ wv, const float* __restrict__ bq,
                                 const float* __restrict__ bk, const float* __restrict__ bv) {
    int i = blockIdx.x * blockDim.x + threadIdx.x;
    const int total = QKV_N * D_MODEL;
    if (i < total) {
        int col = i / D_MODEL;      // output feature 0..1151
        int d   = i % D_MODEL;      // input feature
        int which = col / D_MODEL;
        int hc    = col % D_MODEL;
        int h = hc / HS, e = hc % HS;
        const float* w = (which == 0) ? wq : (which == 1) ? wk : wv;
        g_WqkvT[i] = __float2bfloat16(w[((size_t)h * D_MODEL + d) * HS + e]);
    }
    if (i < QKV_N) {
        int which = i / D_MODEL;
        int hc    = i % D_MODEL;
        int h = hc / HS, e = hc % HS;
        const float* bsrc = (which == 0) ? bq : (which == 1) ? bk : bv;
        g_bqkv[i] = bsrc[h * HS + e];
    }
}

// src[Kd][Nd] fp32 row-major -> dst[Nd][Kd] bf16 row-major
__global__ void transpose_bf_kernel(const float* __restrict__ src, __nv_bfloat16* __restrict__ dst,
                                    int Kd, int Nd) {
    int i = blockIdx.x * blockDim.x + threadIdx.x;
    if (i < Kd * Nd) {
        int n = i / Kd, k = i % Kd;
        dst[i] = __float2bfloat16(src[(size_t)k * Nd + n]);
    }
}

// ---------------------------------------------------------------------------
// LayerNorm: one warp per token row; writes fp32 AND bf16 outputs
// ---------------------------------------------------------------------------
__global__ void ln_kernel(const float* __restrict__ in, const float* __restrict__ gain,
                          const float* __restrict__ bias, float* __restrict__ out,
                          __nv_bfloat16* __restrict__ outb) {
    int warp = (blockIdx.x * blockDim.x + threadIdx.x) >> 5;
    int lane = threadIdx.x & 31;
    if (warp >= M_TOK) return;
    const float4* row = (const float4*)(in + (size_t)warp * D_MODEL);
    float4 v[3];
    float s = 0.f, s2 = 0.f;
#pragma unroll
    for (int j = 0; j < 3; j++) {
        v[j] = row[lane + 32 * j];
        s  += v[j].x + v[j].y + v[j].z + v[j].w;
        s2 += v[j].x * v[j].x + v[j].y * v[j].y + v[j].z * v[j].z + v[j].w * v[j].w;
    }
#pragma unroll
    for (int o = 16; o; o >>= 1) {
        s  += __shfl_xor_sync(0xffffffffu, s,  o);
        s2 += __shfl_xor_sync(0xffffffffu, s2, o);
    }
    float mean = s * (1.0f / D_MODEL);
    float var  = s2 * (1.0f / D_MODEL) - mean * mean;
    float inv  = rsqrtf(var + 1e-5f);
    float4* orow = (float4*)(out + (size_t)warp * D_MODEL);
    __nv_bfloat16* brow = outb + (size_t)warp * D_MODEL;
#pragma unroll
    for (int j = 0; j < 3; j++) {
        int idx = lane + 32 * j;
        float4 g4 = ((const float4*)gain)[idx];
        float4 b4 = ((const float4*)bias)[idx];
        float4 o;
        o.x = (v[j].x - mean) * inv * g4.x + b4.x;
        o.y = (v[j].y - mean) * inv * g4.y + b4.y;
        o.z = (v[j].z - mean) * inv * g4.z + b4.z;
        o.w = (v[j].w - mean) * inv * g4.w + b4.w;
        orow[idx] = o;
        __nv_bfloat162 p0 = __floats2bfloat162_rn(o.x, o.y);
        __nv_bfloat162 p1 = __floats2bfloat162_rn(o.z, o.w);
        uint2 packed;
        packed.x = *(uint32_t*)&p0;
        packed.y = *(uint32_t*)&p1;
        *(uint2*)&brow[idx * 4] = packed;
    }
}

// ---------------------------------------------------------------------------
// bf16 HMMA GEMM: C[M,N] = A[M,K] @ Bw[N,K]^T (+bias)(relu)(+res)
// 128x128 tile, BK=32, 256 threads (8 warps 2x4, warp tile 64x32),
// mma.sync.m16n8k16, cp.async double-buffer.
// ---------------------------------------------------------------------------
#define BK  32
#define AST 40   // padded smem row stride in bf16 elems (80B): conflict-free

template <bool BIAS, bool RES, bool RELU, bool OUTBF>
__global__ __launch_bounds__(256)
void bgemm(const __nv_bfloat16* __restrict__ A, const __nv_bfloat16* __restrict__ Bw,
           const float* __restrict__ bias, const float* __restrict__ Rsd,
           void* __restrict__ Cout, int N, int K) {
    __shared__ __nv_bfloat16 As[2][128 * AST];
    __shared__ __nv_bfloat16 Bs[2][128 * AST];

    const int tid = threadIdx.x;
    const int lane = tid & 31, warp = tid >> 5;
    const int warp_m = warp & 1, warp_n = warp >> 1;
    const int g = lane >> 2, tg = lane & 3;
    const int bm = blockIdx.y * 128, bn = blockIdx.x * 128;

    const uint32_t sA[2] = { smem_u32(As[0]), smem_u32(As[1]) };
    const uint32_t sB[2] = { smem_u32(Bs[0]), smem_u32(Bs[1]) };

    auto issue = [&](int k0, int buf) {
#pragma unroll
        for (int i = 0; i < 2; i++) {
            int idx = tid + i * 256;
            int row = idx >> 2, seg = idx & 3;
            cp16(sA[buf] + (row * AST + seg * 8) * 2,
                 A + (size_t)(bm + row) * K + k0 + seg * 8);
        }
#pragma unroll
        for (int i = 0; i < 2; i++) {
            int idx = tid + i * 256;
            int row = idx >> 2, seg = idx & 3;
            cp16(sB[buf] + (row * AST + seg * 8) * 2,
                 Bw + (size_t)(bn + row) * K + k0 + seg * 8);
        }
        asm volatile("cp.async.commit_group;" ::: "memory");
    };

    float acc[4][4][4] = {};

    issue(0, 0);
    const int NC = K / BK;
    for (int c = 0; c < NC; c++) {
        const int buf = c & 1;
        if (c + 1 < NC) {
            issue((c + 1) * BK, buf ^ 1);
            asm volatile("cp.async.wait_group 1;" ::: "memory");
        } else {
            asm volatile("cp.async.wait_group 0;" ::: "memory");
        }
        __syncthreads();

        const __nv_bfloat16* as = As[buf];
        const __nv_bfloat16* bs = Bs[buf];
#pragma unroll
        for (int ks = 0; ks < BK; ks += 16) {
            uint32_t afr[4][4], bfr[4][2];
#pragma unroll
            for (int mt = 0; mt < 4; mt++) {
                int m0 = warp_m * 64 + mt * 16 + g;
                afr[mt][0] = *(const uint32_t*)&as[m0 * AST + ks + tg * 2];
                afr[mt][1] = *(const uint32_t*)&as[(m0 + 8) * AST + ks + tg * 2];
                afr[mt][2] = *(const uint32_t*)&as[m0 * AST + ks + 8 + tg * 2];
                afr[mt][3] = *(const uint32_t*)&as[(m0 + 8) * AST + ks + 8 + tg * 2];
            }
#pragma unroll
            for (int nt = 0; nt < 4; nt++) {
                int n0 = warp_n * 32 + nt * 8 + g;
                bfr[nt][0] = *(const uint32_t*)&bs[n0 * AST + ks + tg * 2];
                bfr[nt][1] = *(const uint32_t*)&bs[n0 * AST + ks + 8 + tg * 2];
            }
#pragma unroll
            for (int mt = 0; mt < 4; mt++)
#pragma unroll
                for (int nt = 0; nt < 4; nt++)
                    mma_bf16(acc[mt][nt], afr[mt], bfr[nt]);
        }
        __syncthreads();
    }

    // epilogue
    float* Cf = (float*)Cout;
    __nv_bfloat16* Cb = (__nv_bfloat16*)Cout;
#pragma unroll
    for (int mt = 0; mt < 4; mt++) {
#pragma unroll
        for (int half = 0; half < 2; half++) {
            int row = bm + warp_m * 64 + mt * 16 + g + half * 8;
#pragma unroll
            for (int nt = 0; nt < 4; nt++) {
                int col = bn + warp_n * 32 + nt * 8 + tg * 2;
                float vx = acc[mt][nt][half * 2 + 0];
                float vy = acc[mt][nt][half * 2 + 1];
                if (BIAS) {
                    float2 b2 = *(const float2*)&bias[col];
                    vx += b2.x; vy += b2.y;
                }
                if (RELU) { vx = fmaxf(vx, 0.f); vy = fmaxf(vy, 0.f); }
                if (RES) {
                    float2 r2 = *(const float2*)&Rsd[(size_t)row * N + col];
                    vx += r2.x; vy += r2.y;
                }
                if (OUTBF) {
                    __nv_bfloat162 p = __floats2bfloat162_rn(vx, vy);
                    *(__nv_bfloat162*)&Cb[(size_t)row * N + col] = p;
                } else {
                    *(float2*)&Cf[(size_t)row * N + col] = make_float2(vx, vy);
                }
            }
        }
    }
}

// ---------------------------------------------------------------------------
// Causal attention: one CTA (128 threads) per (batch, head).
// fp32 math, float4 smem access, bf16 output for the projection GEMM.
// ---------------------------------------------------------------------------
#define KVS 52   // padded K/V row stride (floats): 208B, 16B-aligned

__global__ __launch_bounds__(128) void attn_kernel(__nv_bfloat16* __restrict__ out) {
    const int bh = blockIdx.x;
    const int b = bh >> 3;
    const int h = bh & 7;
    const float* qkv = g_big;

    __shared__ float ks[T_SEQ][KVS];
    __shared__ float vs[T_SEQ][KVS];
    __shared__ float es[T_SEQ][T_SEQ + 1];

    const int tid = threadIdx.x;

    // cooperative float4 load of K, V tiles (64 rows x 12 float4)
    for (int i = tid; i < T_SEQ * 12; i += 128) {
        int r = i / 12, c4 = i % 12;
        size_t base = (size_t)(b * T_SEQ + r) * QKV_N + h * HS + c4 * 4;
        *(float4*)&ks[r][c4 * 4] = *(const float4*)&qkv[base + D_MODEL];
        *(float4*)&vs[r][c4 * 4] = *(const float4*)&qkv[base + 2 * D_MODEL];
    }
    __syncthreads();

    const int t    = tid >> 1;
    const int half = tid & 1;
    const int eoff = half * 24;
    const unsigned pairmask = 0x3u << (tid & 30);

    const size_t qbase = (size_t)(b * T_SEQ + t) * QKV_N + h * HS + eoff;
    float q[24];
#pragma unroll
    for (int e4 = 0; e4 < 24; e4 += 4) {
        float4 q4 = *(const float4*)&qkv[qbase + e4];
        q[e4] = q4.x; q[e4 + 1] = q4.y; q[e4 + 2] = q4.z; q[e4 + 3] = q4.w;
    }

    const float scale = 0.14433756729740643f;  // 1/sqrt(48)
    float mx = -1e30f;
    for (int s = 0; s <= t; s++) {
        const float4* kk = (const float4*)&ks[s][eoff];
        float part = 0.f;
#pragma unroll
        for (int j = 0; j < 6; j++) {
            float4 k4 = kk[j];
            part += q[j * 4] * k4.x + q[j * 4 + 1] * k4.y
                  + q[j * 4 + 2] * k4.z + q[j * 4 + 3] * k4.w;
        }
        float d = (part + __shfl_xor_sync(pairmask, part, 1)) * scale;
        if (!half) es[t][s] = d;
        mx = fmaxf(mx, d);
    }
    __syncwarp();

    float sum = 0.f;
    float acc[24];
#pragma unroll
    for (int e = 0; e < 24; e++) acc[e] = 0.f;
    for (int s = 0; s <= t; s++) {
        float p = __expf(es[t][s] - mx);
        sum += p;
        const float4* vv = (const float4*)&vs[s][eoff];
#pragma unroll
        for (int j = 0; j < 6; j++) {
            float4 v4 = vv[j];
            acc[j * 4]     += p * v4.x;
            acc[j * 4 + 1] += p * v4.y;
            acc[j * 4 + 2] += p * v4.z;
            acc[j * 4 + 3] += p * v4.w;
        }
    }
    const float inv = 1.0f / sum;

    const size_t ob = (size_t)(b * T_SEQ + t) * D_MODEL + h * HS + eoff;
    uint32_t packed[12];
#pragma unroll
    for (int j = 0; j < 12; j++) {
        __nv_bfloat162 p = __floats2bfloat162_rn(acc[2 * j] * inv, acc[2 * j + 1] * inv);
        packed[j] = *(uint32_t*)&p;
    }
#pragma unroll
    for (int j = 0; j < 3; j++) {
        uint4 st = make_uint4(packed[j * 4], packed[j * 4 + 1],
                              packed[j * 4 + 2], packed[j * 4 + 3]);
        *(uint4*)&out[ob + j * 8] = st;
    }
}

// ---------------------------------------------------------------------------
// Launcher
// ---------------------------------------------------------------------------
extern "C" void kernel_launch(void* const* d_in, const int* in_sizes, int n_in,
                              void* d_out, int out_size) {
    (void)in_sizes; (void)n_in; (void)out_size;
    const float* x  = (const float*)d_in[0];
    const float* wq = (const float*)d_in[1];
    const float* bq = (const float*)d_in[2];
    const float* wk = (const float*)d_in[3];
    const float* bk = (const float*)d_in[4];
    const float* wv = (const float*)d_in[5];
    const float* bv = (const float*)d_in[6];
    const float* wo = (const float*)d_in[7];
    const float* bo = (const float*)d_in[8];
    const float* w1 = (const float*)d_in[9];
    const float* b1 = (const float*)d_in[10];
    const float* w2 = (const float*)d_in[11];
    const float* b2 = (const float*)d_in[12];
    const float* g1 = (const float*)d_in[13];
    const float* be1 = (const float*)d_in[14];
    const float* g2 = (const float*)d_in[15];
    const float* be2 = (const float*)d_in[16];
    float* out = (float*)d_out;

    float *p_h1, *p_h2, *p_res, *p_big, *p_bqkv;
    __nv_bfloat16 *p_h1b, *p_h2b, *p_attnb, *p_midb, *p_WqkvT, *p_WoT, *p_W1T, *p_W2T;
    cudaGetSymbolAddress((void**)&p_h1, g_h1);
    cudaGetSymbolAddress((void**)&p_h1b, g_h1b);
    cudaGetSymbolAddress((void**)&p_h2, g_h2);
    cudaGetSymbolAddress((void**)&p_h2b, g_h2b);
    cudaGetSymbolAddress((void**)&p_res, g_res);
    cudaGetSymbolAddress((void**)&p_big, g_big);
    cudaGetSymbolAddress((void**)&p_attnb, g_attnb);
    cudaGetSymbolAddress((void**)&p_midb, g_midb);
    cudaGetSymbolAddress((void**)&p_WqkvT, g_WqkvT);
    cudaGetSymbolAddress((void**)&p_bqkv, g_bqkv);
    cudaGetSymbolAddress((void**)&p_WoT, g_WoT);
    cudaGetSymbolAddress((void**)&p_W1T, g_W1T);
    cudaGetSymbolAddress((void**)&p_W2T, g_W2T);

    // 0. weight repacks -> bf16 [N][K]
    pack_qkvT_kernel<<<(QKV_N * D_MODEL + 255) / 256, 256>>>(wq, wk, wv, bq, bk, bv);
    transpose_bf_kernel<<<(D_MODEL * D_MODEL + 255) / 256, 256>>>(wo, p_WoT, D_MODEL, D_MODEL);
    transpose_bf_kernel<<<(D_MODEL * D_FF + 255) / 256, 256>>>(w1, p_W1T, D_MODEL, D_FF);
    transpose_bf_kernel<<<(D_FF * D_MODEL + 255) / 256, 256>>>(w2, p_W2T, D_FF, D_MODEL);

    // 1. LN1: x -> h1 (fp32) + h1b (bf16)
    ln_kernel<<<(M_TOK * 32) / 256, 256>>>(x, g1, be1, p_h1, p_h1b);

    // 2. QKV GEMM: h1b @ WqkvT^T + bqkv -> g_big (fp32)
    bgemm<true, false, false, false><<<dim3(QKV_N / 128, M_TOK / 128), 256>>>(
        p_h1b, p_WqkvT, p_bqkv, nullptr, p_big, QKV_N, D_MODEL);

    // 3. attention -> attnb (bf16)
    attn_kernel<<<BATCH * NH, 128>>>(p_attnb);

    // 4. output projection + residual: attnb @ WoT^T + bo + h1 -> res (fp32)
    bgemm<true, true, false, false><<<dim3(D_MODEL / 128, M_TOK / 128), 256>>>(
        p_attnb, p_WoT, bo, p_h1, p_res, D_MODEL, D_MODEL);

    // 5. LN2: res -> h2 (fp32) + h2b (bf16)
    ln_kernel<<<(M_TOK * 32) / 256, 256>>>(p_res, g2, be2, p_h2, p_h2b);

    // 6. FF1 + ReLU: h2b @ W1T^T + b1 -> midb (bf16)
    bgemm<true, false, true, true><<<dim3(D_FF / 128, M_TOK / 128), 256>>>(
        p_h2b, p_W1T, b1, nullptr, p_midb, D_FF, D_MODEL);

    // 7. FF2 + bias + residual: midb @ W2T^T + b2 + h2 -> out (fp32)
    bgemm<true, true, false, false><<<dim3(D_MODEL / 128, M_TOK / 128), 256>>>(
        p_midb, p_W2T, b2, p_h2, out, D_MODEL, D_FF);
}

// round 6
// speedup vs baseline: 4.9951x; 1.1068x over previous
#include <cuda_runtime.h>
#include <cuda_bf16.h>
#include <math.h>
#include <stdint.h>

// ---------------------------------------------------------------------------
// Problem constants
// ---------------------------------------------------------------------------
#define BATCH   2048
#define T_SEQ   64
#define D_MODEL 384
#define NH      8
#define HS      48
#define D_FF    1536
#define M_TOK   (BATCH * T_SEQ)          // 131072
#define QKV_N   (3 * D_MODEL)            // 1152

// ---------------------------------------------------------------------------
// Scratch (static device globals)
// ---------------------------------------------------------------------------
__device__ float          g_h1  [(size_t)M_TOK * D_MODEL];
__device__ __nv_bfloat16  g_h1b [(size_t)M_TOK * D_MODEL];
__device__ float          g_h2  [(size_t)M_TOK * D_MODEL];
__device__ __nv_bfloat16  g_h2b [(size_t)M_TOK * D_MODEL];
__device__ float          g_res [(size_t)M_TOK * D_MODEL];
__device__ float          g_big [(size_t)M_TOK * QKV_N];    // QKV fp32
__device__ __nv_bfloat16  g_attnb[(size_t)M_TOK * D_MODEL]; // attn out bf16
__device__ __nv_bfloat16  g_midb[(size_t)M_TOK * D_FF];     // FF mid bf16
__device__ __nv_bfloat16  g_WqkvT[(size_t)QKV_N * D_MODEL]; // [1152][384] bf16
__device__ float          g_bqkv [QKV_N];
__device__ __nv_bfloat16  g_WoT  [(size_t)D_MODEL * D_MODEL];
__device__ __nv_bfloat16  g_W1T  [(size_t)D_FF * D_MODEL];
__device__ __nv_bfloat16  g_W2T  [(size_t)D_MODEL * D_FF];

// ---------------------------------------------------------------------------
// Helpers
// ---------------------------------------------------------------------------
__device__ __forceinline__ uint32_t smem_u32(const void* p) {
    uint32_t a;
    asm("{ .reg .u64 t; cvta.to.shared.u64 t, %1; cvt.u32.u64 %0, t; }" : "=r"(a) : "l"(p));
    return a;
}
__device__ __forceinline__ void cp16(uint32_t dst, const void* src) {
    asm volatile("cp.async.cg.shared.global [%0], [%1], 16;" :: "r"(dst), "l"(src));
}
__device__ __forceinline__ void mma_bf16(float* c, const uint32_t* a, const uint32_t* b) {
    asm volatile(
        "mma.sync.aligned.m16n8k16.row.col.f32.bf16.bf16.f32 "
        "{%0,%1,%2,%3}, {%4,%5,%6,%7}, {%8,%9}, {%0,%1,%2,%3};"
        : "+f"(c[0]), "+f"(c[1]), "+f"(c[2]), "+f"(c[3])
        : "r"(a[0]), "r"(a[1]), "r"(a[2]), "r"(a[3]), "r"(b[0]), "r"(b[1]));
}
__device__ __forceinline__ void mma_tf32(float* c, const uint32_t* a, const uint32_t* b) {
    asm volatile(
        "mma.sync.aligned.m16n8k8.row.col.f32.tf32.tf32.f32 "
        "{%0,%1,%2,%3}, {%4,%5,%6,%7}, {%8,%9}, {%0,%1,%2,%3};"
        : "+f"(c[0]), "+f"(c[1]), "+f"(c[2]), "+f"(c[3])
        : "r"(a[0]), "r"(a[1]), "r"(a[2]), "r"(a[3]), "r"(b[0]), "r"(b[1]));
}
__device__ __forceinline__ uint32_t f2tf32(float f) {
    uint32_t u;
    asm("cvt.rna.tf32.f32 %0, %1;" : "=r"(u) : "f"(f));
    return u;
}
__device__ __forceinline__ uint32_t packbf(float x, float y) {
    __nv_bfloat162 p = __floats2bfloat162_rn(x, y);
    return *(uint32_t*)&p;
}

// ---------------------------------------------------------------------------
// Weight repack kernels (fp32 -> bf16, transposed to [N][K] K-major)
// ---------------------------------------------------------------------------
__global__ void pack_qkvT_kernel(const float* __restrict__ wq, const float* __restrict__ wk,
                                 const float* __restrict__ wv, const float* __restrict__ bq,
                                 const float* __restrict__ bk, const float* __restrict__ bv) {
    int i = blockIdx.x * blockDim.x + threadIdx.x;
    const int total = QKV_N * D_MODEL;
    if (i < total) {
        int col = i / D_MODEL;
        int d   = i % D_MODEL;
        int which = col / D_MODEL;
        int hc    = col % D_MODEL;
        int h = hc / HS, e = hc % HS;
        const float* w = (which == 0) ? wq : (which == 1) ? wk : wv;
        g_WqkvT[i] = __float2bfloat16(w[((size_t)h * D_MODEL + d) * HS + e]);
    }
    if (i < QKV_N) {
        int which = i / D_MODEL;
        int hc    = i % D_MODEL;
        int h = hc / HS, e = hc % HS;
        const float* bsrc = (which == 0) ? bq : (which == 1) ? bk : bv;
        g_bqkv[i] = bsrc[h * HS + e];
    }
}

__global__ void transpose_bf_kernel(const float* __restrict__ src, __nv_bfloat16* __restrict__ dst,
                                    int Kd, int Nd) {
    int i = blockIdx.x * blockDim.x + threadIdx.x;
    if (i < Kd * Nd) {
        int n = i / Kd, k = i % Kd;
        dst[i] = __float2bfloat16(src[(size_t)k * Nd + n]);
    }
}

// ---------------------------------------------------------------------------
// LayerNorm: one warp per token row; writes fp32 AND bf16 outputs
// ---------------------------------------------------------------------------
__global__ void ln_kernel(const float* __restrict__ in, const float* __restrict__ gain,
                          const float* __restrict__ bias, float* __restrict__ out,
                          __nv_bfloat16* __restrict__ outb) {
    int warp = (blockIdx.x * blockDim.x + threadIdx.x) >> 5;
    int lane = threadIdx.x & 31;
    if (warp >= M_TOK) return;
    const float4* row = (const float4*)(in + (size_t)warp * D_MODEL);
    float4 v[3];
    float s = 0.f, s2 = 0.f;
#pragma unroll
    for (int j = 0; j < 3; j++) {
        v[j] = row[lane + 32 * j];
        s  += v[j].x + v[j].y + v[j].z + v[j].w;
        s2 += v[j].x * v[j].x + v[j].y * v[j].y + v[j].z * v[j].z + v[j].w * v[j].w;
    }
#pragma unroll
    for (int o = 16; o; o >>= 1) {
        s  += __shfl_xor_sync(0xffffffffu, s,  o);
        s2 += __shfl_xor_sync(0xffffffffu, s2, o);
    }
    float mean = s * (1.0f / D_MODEL);
    float var  = s2 * (1.0f / D_MODEL) - mean * mean;
    float inv  = rsqrtf(var + 1e-5f);
    float4* orow = (float4*)(out + (size_t)warp * D_MODEL);
    __nv_bfloat16* brow = outb + (size_t)warp * D_MODEL;
#pragma unroll
    for (int j = 0; j < 3; j++) {
        int idx = lane + 32 * j;
        float4 g4 = ((const float4*)gain)[idx];
        float4 b4 = ((const float4*)bias)[idx];
        float4 o;
        o.x = (v[j].x - mean) * inv * g4.x + b4.x;
        o.y = (v[j].y - mean) * inv * g4.y + b4.y;
        o.z = (v[j].z - mean) * inv * g4.z + b4.z;
        o.w = (v[j].w - mean) * inv * g4.w + b4.w;
        orow[idx] = o;
        uint2 packed;
        packed.x = packbf(o.x, o.y);
        packed.y = packbf(o.z, o.w);
        *(uint2*)&brow[idx * 4] = packed;
    }
}

// ---------------------------------------------------------------------------
// bf16 HMMA GEMM (unchanged from R5): 128x128, BK=32, 256 thr, cp.async x2
// ---------------------------------------------------------------------------
#define BK  32
#define AST 40

template <bool BIAS, bool RES, bool RELU, bool OUTBF>
__global__ __launch_bounds__(256)
void bgemm(const __nv_bfloat16* __restrict__ A, const __nv_bfloat16* __restrict__ Bw,
           const float* __restrict__ bias, const float* __restrict__ Rsd,
           void* __restrict__ Cout, int N, int K) {
    __shared__ __nv_bfloat16 As[2][128 * AST];
    __shared__ __nv_bfloat16 Bs[2][128 * AST];

    const int tid = threadIdx.x;
    const int lane = tid & 31, warp = tid >> 5;
    const int warp_m = warp & 1, warp_n = warp >> 1;
    const int g = lane >> 2, tg = lane & 3;
    const int bm = blockIdx.y * 128, bn = blockIdx.x * 128;

    const uint32_t sA[2] = { smem_u32(As[0]), smem_u32(As[1]) };
    const uint32_t sB[2] = { smem_u32(Bs[0]), smem_u32(Bs[1]) };

    auto issue = [&](int k0, int buf) {
#pragma unroll
        for (int i = 0; i < 2; i++) {
            int idx = tid + i * 256;
            int row = idx >> 2, seg = idx & 3;
            cp16(sA[buf] + (row * AST + seg * 8) * 2,
                 A + (size_t)(bm + row) * K + k0 + seg * 8);
        }
#pragma unroll
        for (int i = 0; i < 2; i++) {
            int idx = tid + i * 256;
            int row = idx >> 2, seg = idx & 3;
            cp16(sB[buf] + (row * AST + seg * 8) * 2,
                 Bw + (size_t)(bn + row) * K + k0 + seg * 8);
        }
        asm volatile("cp.async.commit_group;" ::: "memory");
    };

    float acc[4][4][4] = {};

    issue(0, 0);
    const int NC = K / BK;
    for (int c = 0; c < NC; c++) {
        const int buf = c & 1;
        if (c + 1 < NC) {
            issue((c + 1) * BK, buf ^ 1);
            asm volatile("cp.async.wait_group 1;" ::: "memory");
        } else {
            asm volatile("cp.async.wait_group 0;" ::: "memory");
        }
        __syncthreads();

        const __nv_bfloat16* as = As[buf];
        const __nv_bfloat16* bs = Bs[buf];
#pragma unroll
        for (int ks = 0; ks < BK; ks += 16) {
            uint32_t afr[4][4], bfr[4][2];
#pragma unroll
            for (int mt = 0; mt < 4; mt++) {
                int m0 = warp_m * 64 + mt * 16 + g;
                afr[mt][0] = *(const uint32_t*)&as[m0 * AST + ks + tg * 2];
                afr[mt][1] = *(const uint32_t*)&as[(m0 + 8) * AST + ks + tg * 2];
                afr[mt][2] = *(const uint32_t*)&as[m0 * AST + ks + 8 + tg * 2];
                afr[mt][3] = *(const uint32_t*)&as[(m0 + 8) * AST + ks + 8 + tg * 2];
            }
#pragma unroll
            for (int nt = 0; nt < 4; nt++) {
                int n0 = warp_n * 32 + nt * 8 + g;
                bfr[nt][0] = *(const uint32_t*)&bs[n0 * AST + ks + tg * 2];
                bfr[nt][1] = *(const uint32_t*)&bs[n0 * AST + ks + 8 + tg * 2];
            }
#pragma unroll
            for (int mt = 0; mt < 4; mt++)
#pragma unroll
                for (int nt = 0; nt < 4; nt++)
                    mma_bf16(acc[mt][nt], afr[mt], bfr[nt]);
        }
        __syncthreads();
    }

    float* Cf = (float*)Cout;
    __nv_bfloat16* Cb = (__nv_bfloat16*)Cout;
#pragma unroll
    for (int mt = 0; mt < 4; mt++) {
#pragma unroll
        for (int half = 0; half < 2; half++) {
            int row = bm + warp_m * 64 + mt * 16 + g + half * 8;
#pragma unroll
            for (int nt = 0; nt < 4; nt++) {
                int col = bn + warp_n * 32 + nt * 8 + tg * 2;
                float vx = acc[mt][nt][half * 2 + 0];
                float vy = acc[mt][nt][half * 2 + 1];
                if (BIAS) {
                    float2 b2 = *(const float2*)&bias[col];
                    vx += b2.x; vy += b2.y;
                }
                if (RELU) { vx = fmaxf(vx, 0.f); vy = fmaxf(vy, 0.f); }
                if (RES) {
                    float2 r2 = *(const float2*)&Rsd[(size_t)row * N + col];
                    vx += r2.x; vy += r2.y;
                }
                if (OUTBF) {
                    *(uint32_t*)&Cb[(size_t)row * N + col] = packbf(vx, vy);
                } else {
                    *(float2*)&Cf[(size_t)row * N + col] = make_float2(vx, vy);
                }
            }
        }
    }
}

// ---------------------------------------------------------------------------
// Tensor-core causal attention: one CTA (4 warps) per (batch, head).
// QK^T in tf32 (fp32 inputs), fp32 softmax, PV in bf16 with C->A frag reuse.
// Warp w owns score rows 16w..16w+15.
// ---------------------------------------------------------------------------
__global__ __launch_bounds__(128) void attn_kernel(__nv_bfloat16* __restrict__ out) {
    const int bh = blockIdx.x;
    const int b = bh >> 3, h = bh & 7;
    const float* qkv = g_big;

    __shared__ float qs[T_SEQ][52];            // Q [s][e] fp32
    __shared__ float ksm[T_SEQ][52];           // K [s][e] fp32
    __shared__ __nv_bfloat16 vt[HS][72];       // V^T [e][s] bf16

    const int tid = threadIdx.x;
    const int lane = tid & 31, warp = tid >> 5;
    const int g = lane >> 2, tg = lane & 3;

    // cooperative load: Q,K fp32; V transposed bf16
    for (int i = tid; i < T_SEQ * 12; i += 128) {
        int r = i / 12, c4 = (i % 12) * 4;
        size_t base = (size_t)(b * T_SEQ + r) * QKV_N + h * HS + c4;
        *(float4*)&qs[r][c4]  = *(const float4*)&qkv[base];
        *(float4*)&ksm[r][c4] = *(const float4*)&qkv[base + D_MODEL];
        float4 v4 = *(const float4*)&qkv[base + 2 * D_MODEL];
        vt[c4 + 0][r] = __float2bfloat16(v4.x);
        vt[c4 + 1][r] = __float2bfloat16(v4.y);
        vt[c4 + 2][r] = __float2bfloat16(v4.z);
        vt[c4 + 3][r] = __float2bfloat16(v4.w);
    }
    __syncthreads();

    const int m0 = warp * 16;

    // ---- S = Q @ K^T  (tf32) ----
    float sacc[8][4] = {};
#pragma unroll
    for (int ks = 0; ks < HS; ks += 8) {
        uint32_t a[4];
        a[0] = f2tf32(qs[m0 + g][ks + tg]);
        a[1] = f2tf32(qs[m0 + g + 8][ks + tg]);
        a[2] = f2tf32(qs[m0 + g][ks + tg + 4]);
        a[3] = f2tf32(qs[m0 + g + 8][ks + tg + 4]);
#pragma unroll
        for (int nt = 0; nt < 8; nt++) {
            uint32_t bf[2];
            bf[0] = f2tf32(ksm[nt * 8 + g][ks + tg]);
            bf[1] = f2tf32(ksm[nt * 8 + g][ks + tg + 4]);
            mma_tf32(sacc[nt], a, bf);
        }
    }

    // ---- scale + causal mask + softmax (rows m0+g and m0+g+8) ----
    const float scale = 0.14433756729740643f;  // 1/sqrt(48)
    const int row0 = m0 + g, row1 = m0 + g + 8;
    float mx0 = -1e30f, mx1 = -1e30f;
#pragma unroll
    for (int nt = 0; nt < 8; nt++) {
#pragma unroll
        for (int j = 0; j < 2; j++) {
            int col = nt * 8 + tg * 2 + j;
            float s0 = sacc[nt][j] * scale;
            float s1 = sacc[nt][2 + j] * scale;
            if (col > row0) s0 = -1e30f;
            if (col > row1) s1 = -1e30f;
            sacc[nt][j] = s0;     sacc[nt][2 + j] = s1;
            mx0 = fmaxf(mx0, s0); mx1 = fmaxf(mx1, s1);
        }
    }
    mx0 = fmaxf(mx0, __shfl_xor_sync(0xffffffffu, mx0, 1));
    mx0 = fmaxf(mx0, __shfl_xor_sync(0xffffffffu, mx0, 2));
    mx1 = fmaxf(mx1, __shfl_xor_sync(0xffffffffu, mx1, 1));
    mx1 = fmaxf(mx1, __shfl_xor_sync(0xffffffffu, mx1, 2));

    float sum0 = 0.f, sum1 = 0.f;
#pragma unroll
    for (int nt = 0; nt < 8; nt++) {
#pragma unroll
        for (int j = 0; j < 2; j++) {
            float e0 = __expf(sacc[nt][j] - mx0);
            float e1 = __expf(sacc[nt][2 + j] - mx1);
            sacc[nt][j] = e0;     sacc[nt][2 + j] = e1;
            sum0 += e0;           sum1 += e1;
        }
    }
    sum0 += __shfl_xor_sync(0xffffffffu, sum0, 1);
    sum0 += __shfl_xor_sync(0xffffffffu, sum0, 2);
    sum1 += __shfl_xor_sync(0xffffffffu, sum1, 1);
    sum1 += __shfl_xor_sync(0xffffffffu, sum1, 2);
    const float inv0 = 1.0f / sum0, inv1 = 1.0f / sum1;

    // ---- O = P @ V  (bf16; P A-frags come directly from S C-frags) ----
    float o[6][4] = {};
#pragma unroll
    for (int ks = 0; ks < 4; ks++) {
        uint32_t a[4];
        a[0] = packbf(sacc[2 * ks][0],     sacc[2 * ks][1]);
        a[1] = packbf(sacc[2 * ks][2],     sacc[2 * ks][3]);
        a[2] = packbf(sacc[2 * ks + 1][0], sacc[2 * ks + 1][1]);
        a[3] = packbf(sacc[2 * ks + 1][2], sacc[2 * ks + 1][3]);
#pragma unroll
        for (int nt = 0; nt < 6; nt++) {
            uint32_t bf[2];
            bf[0] = *(const uint32_t*)&vt[nt * 8 + g][ks * 16 + tg * 2];
            bf[1] = *(const uint32_t*)&vt[nt * 8 + g][ks * 16 + 8 + tg * 2];
            mma_bf16(o[nt], a, bf);
        }
    }

    // ---- normalize + store bf16 ----
    const size_t ob0 = (size_t)(b * T_SEQ + row0) * D_MODEL + h * HS;
    const size_t ob1 = (size_t)(b * T_SEQ + row1) * D_MODEL + h * HS;
#pragma unroll
    for (int nt = 0; nt < 6; nt++) {
        int col = nt * 8 + tg * 2;
        *(uint32_t*)&out[ob0 + col] = packbf(o[nt][0] * inv0, o[nt][1] * inv0);
        *(uint32_t*)&out[ob1 + col] = packbf(o[nt][2] * inv1, o[nt][3] * inv1);
    }
}

// ---------------------------------------------------------------------------
// Launcher
// ---------------------------------------------------------------------------
extern "C" void kernel_launch(void* const* d_in, const int* in_sizes, int n_in,
                              void* d_out, int out_size) {
    (void)in_sizes; (void)n_in; (void)out_size;
    const float* x  = (const float*)d_in[0];
    const float* wq = (const float*)d_in[1];
    const float* bq = (const float*)d_in[2];
    const float* wk = (const float*)d_in[3];
    const float* bk = (const float*)d_in[4];
    const float* wv = (const float*)d_in[5];
    const float* bv = (const float*)d_in[6];
    const float* wo = (const float*)d_in[7];
    const float* bo = (const float*)d_in[8];
    const float* w1 = (const float*)d_in[9];
    const float* b1 = (const float*)d_in[10];
    const float* w2 = (const float*)d_in[11];
    const float* b2 = (const float*)d_in[12];
    const float* g1 = (const float*)d_in[13];
    const float* be1 = (const float*)d_in[14];
    const float* g2 = (const float*)d_in[15];
    const float* be2 = (const float*)d_in[16];
    float* out = (float*)d_out;

    float *p_h1, *p_h2, *p_res, *p_big, *p_bqkv;
    __nv_bfloat16 *p_h1b, *p_h2b, *p_attnb, *p_midb, *p_WqkvT, *p_WoT, *p_W1T, *p_W2T;
    cudaGetSymbolAddress((void**)&p_h1, g_h1);
    cudaGetSymbolAddress((void**)&p_h1b, g_h1b);
    cudaGetSymbolAddress((void**)&p_h2, g_h2);
    cudaGetSymbolAddress((void**)&p_h2b, g_h2b);
    cudaGetSymbolAddress((void**)&p_res, g_res);
    cudaGetSymbolAddress((void**)&p_big, g_big);
    cudaGetSymbolAddress((void**)&p_attnb, g_attnb);
    cudaGetSymbolAddress((void**)&p_midb, g_midb);
    cudaGetSymbolAddress((void**)&p_WqkvT, g_WqkvT);
    cudaGetSymbolAddress((void**)&p_bqkv, g_bqkv);
    cudaGetSymbolAddress((void**)&p_WoT, g_WoT);
    cudaGetSymbolAddress((void**)&p_W1T, g_W1T);
    cudaGetSymbolAddress((void**)&p_W2T, g_W2T);

    // 0. weight repacks -> bf16 [N][K]
    pack_qkvT_kernel<<<(QKV_N * D_MODEL + 255) / 256, 256>>>(wq, wk, wv, bq, bk, bv);
    transpose_bf_kernel<<<(D_MODEL * D_MODEL + 255) / 256, 256>>>(wo, p_WoT, D_MODEL, D_MODEL);
    transpose_bf_kernel<<<(D_MODEL * D_FF + 255) / 256, 256>>>(w1, p_W1T, D_MODEL, D_FF);
    transpose_bf_kernel<<<(D_FF * D_MODEL + 255) / 256, 256>>>(w2, p_W2T, D_FF, D_MODEL);

    // 1. LN1: x -> h1 (fp32) + h1b (bf16)
    ln_kernel<<<(M_TOK * 32) / 256, 256>>>(x, g1, be1, p_h1, p_h1b);

    // 2. QKV GEMM: h1b @ WqkvT^T + bqkv -> g_big (fp32)
    bgemm<true, false, false, false><<<dim3(QKV_N / 128, M_TOK / 128), 256>>>(
        p_h1b, p_WqkvT, p_bqkv, nullptr, p_big, QKV_N, D_MODEL);

    // 3. attention (tensor-core) -> attnb (bf16)
    attn_kernel<<<BATCH * NH, 128>>>(p_attnb);

    // 4. output projection + residual: attnb @ WoT^T + bo + h1 -> res (fp32)
    bgemm<true, true, false, false><<<dim3(D_MODEL / 128, M_TOK / 128), 256>>>(
        p_attnb, p_WoT, bo, p_h1, p_res, D_MODEL, D_MODEL);

    // 5. LN2: res -> h2 (fp32) + h2b (bf16)
    ln_kernel<<<(M_TOK * 32) / 256, 256>>>(p_res, g2, be2, p_h2, p_h2b);

    // 6. FF1 + ReLU: h2b @ W1T^T + b1 -> midb (bf16)
    bgemm<true, false, true, true><<<dim3(D_FF / 128, M_TOK / 128), 256>>>(
        p_h2b, p_W1T, b1, nullptr, p_midb, D_FF, D_MODEL);

    // 7. FF2 + bias + residual: midb @ W2T^T + b2 + h2 -> out (fp32)
    bgemm<true, true, false, false><<<dim3(D_MODEL / 128, M_TOK / 128), 256>>>(
        p_midb, p_W2T, b2, p_h2, out, D_MODEL, D_FF);
}